// round 5
// baseline (speedup 1.0000x reference)
#include <cuda_runtime.h>
#include <cstdint>

#define NB    24
#define NP1   25
#define NCOST (NB * NP1)
#define ND    256
#define INFX  1e9f
#define FULL  0xffffffffu

// packed fp32x2 FMA (sm_100+); doubles are 64-bit carriers for f32 pairs
__device__ __forceinline__ double ffma2(double a, double b, double c) {
    double r;
    asm("fma.rn.f32x2 %0, %1, %2, %3;" : "=d"(r) : "d"(a), "d"(b), "d"(c));
    return r;
}
__device__ __forceinline__ float pairsum(double a) {
    return __int_as_float(__double2loint(a)) + __int_as_float(__double2hiint(a));
}
// order-preserving float<->uint for unsigned min-reduction
__device__ __forceinline__ unsigned fenc(float x) {
    unsigned b = __float_as_uint(x);
    return b ^ (((unsigned)((int)b >> 31)) | 0x80000000u);
}
__device__ __forceinline__ float fdec(unsigned k) {
    unsigned m = ((unsigned)((int)(~k) >> 31)) | 0x80000000u;
    return __uint_as_float(k ^ m);
}

// 8-stream folded warp reduction: lane L ends holding the full sum of stream
// m(L) = bit4(L) | bit3(L)<<1 | bit2(L)<<2. 15 shfls, 8-wide ILP at the top.
__device__ __forceinline__ float fold8(
    float q0, float q1, float q2, float q3,
    float q4, float q5, float q6, float q7, int lane)
{
    q0 += __shfl_xor_sync(FULL, q0, 16);
    q1 += __shfl_xor_sync(FULL, q1, 16);
    q2 += __shfl_xor_sync(FULL, q2, 16);
    q3 += __shfl_xor_sync(FULL, q3, 16);
    q4 += __shfl_xor_sync(FULL, q4, 16);
    q5 += __shfl_xor_sync(FULL, q5, 16);
    q6 += __shfl_xor_sync(FULL, q6, 16);
    q7 += __shfl_xor_sync(FULL, q7, 16);
    float t0 = (lane & 16) ? q1 : q0;
    float t1 = (lane & 16) ? q3 : q2;
    float t2 = (lane & 16) ? q5 : q4;
    float t3 = (lane & 16) ? q7 : q6;
    t0 += __shfl_xor_sync(FULL, t0, 8);
    t1 += __shfl_xor_sync(FULL, t1, 8);
    t2 += __shfl_xor_sync(FULL, t2, 8);
    t3 += __shfl_xor_sync(FULL, t3, 8);
    float u0 = (lane & 8) ? t1 : t0;
    float u1 = (lane & 8) ? t3 : t2;
    u0 += __shfl_xor_sync(FULL, u0, 4);
    u1 += __shfl_xor_sync(FULL, u1, 4);
    float v = (lane & 4) ? u1 : u0;
    v += __shfl_xor_sync(FULL, v, 2);
    v += __shfl_xor_sync(FULL, v, 1);
    return v;
}

// ============================================================================
// Fused kernel: CTA = one batch, 192 threads (6 warps).
//  A: stage slots tile -> smem (read once)
//  B: warp w loads its 4 prev rows (i-block w) into regs; one fold8 computes
//     4 prev norms + 4 cur norms (rows w*4..w*4+3 from smem) -> smem
//  C: warp w sweeps 6 j-tiles: 16 dots via ffma2, two fold8s, writers read
//     precomputed inv norms from smem, store cost[24][25] in smem
//  D: warp 0 runs validated warp-JV on smem cost
//  E: all warps gather out rows from smem-resident slots
// ============================================================================
__global__ __launch_bounds__(192) void hungk(
    const float* __restrict__ slots,
    const float* __restrict__ prev,
    float* __restrict__ out)
{
    __shared__ float slots_s[NB * ND];   // 24.5 KB
    __shared__ float cost_s[NCOST];
    __shared__ float ipn_s[NB];
    __shared__ float icn_s[NB];
    __shared__ int   col_s[NB];

    const int tid  = threadIdx.x;
    const int lane = tid & 31;
    const int w    = tid >> 5;           // 0..5
    const int b    = blockIdx.x;

    const float* sb = slots + (size_t)b * NB * ND;
    const float* pb = prev  + (size_t)b * NB * ND;
    float*       ob = out   + (size_t)b * NB * ND;

    // ---- A: stage current slots into smem (coalesced float4) ----
    {
        const float4* g4 = (const float4*)sb;
        float4* s4 = (float4*)slots_s;
        #pragma unroll
        for (int idx = tid; idx < NB * ND / 4; idx += 192)
            s4[idx] = g4[idx];
    }
    __syncthreads();

    // ---- B: prev i-block into registers + all inverse norms ----
    const int i0 = w * 4;
    double2 P[4][2];
    {
        #pragma unroll
        for (int r = 0; r < 4; r++) {
            const double2* pr = (const double2*)(pb + (i0 + r) * ND);
            P[r][0] = pr[lane];
            P[r][1] = pr[lane + 32];
        }
        float np[4], nc[4];
        #pragma unroll
        for (int r = 0; r < 4; r++) {
            double an = 0.0;
            an = ffma2(P[r][0].x, P[r][0].x, an);
            an = ffma2(P[r][0].y, P[r][0].y, an);
            an = ffma2(P[r][1].x, P[r][1].x, an);
            an = ffma2(P[r][1].y, P[r][1].y, an);
            np[r] = pairsum(an);
            const double2* cr = (const double2*)(slots_s + (i0 + r) * ND);
            double2 c0 = cr[lane], c1 = cr[lane + 32];
            double cn = 0.0;
            cn = ffma2(c0.x, c0.x, cn);
            cn = ffma2(c0.y, c0.y, cn);
            cn = ffma2(c1.x, c1.x, cn);
            cn = ffma2(c1.y, c1.y, cn);
            nc[r] = pairsum(cn);
        }
        float v3 = fold8(np[0], np[1], np[2], np[3],
                         nc[0], nc[1], nc[2], nc[3], lane);
        float inv = 1.0f / fmaxf(sqrtf(v3), 1e-12f);
        if ((lane & 3) == 0) {
            // lane -> stream m (bijective over lanes 0,4,...,28)
            int m = ((lane >> 4) & 1) | (((lane >> 3) & 1) << 1) | (((lane >> 2) & 1) << 2);
            if (m < 4) ipn_s[i0 + m]       = inv;
            else       icn_s[i0 + (m - 4)] = inv;
        }
    }
    __syncthreads();

    // ---- C: 6 j-tiles per warp (4x4 outputs each) ----
    {
        const int m = ((lane >> 4) & 1) | (((lane >> 3) & 1) << 1) | (((lane >> 2) & 1) << 2);
        const int a = m >> 2;       // 0..1
        const int c = m & 3;        // 0..3
        const bool writer = ((lane & 3) == 0);
        float ipn1 = 0.f, ipn2 = 0.f;
        if (writer) {
            ipn1 = ipn_s[i0 + a];
            ipn2 = ipn_s[i0 + 2 + a];
        }
        #pragma unroll
        for (int t = 0; t < 6; t++) {
            const int j0 = t * 4;
            double2 C0[4], C1[4];
            #pragma unroll
            for (int r = 0; r < 4; r++) {
                const double2* cr = (const double2*)(slots_s + (j0 + r) * ND);
                C0[r] = cr[lane];
                C1[r] = cr[lane + 32];
            }
            float s[16];
            #pragma unroll
            for (int aa = 0; aa < 4; aa++) {
                #pragma unroll
                for (int cc = 0; cc < 4; cc++) {
                    double acc = 0.0;
                    acc = ffma2(P[aa][0].x, C0[cc].x, acc);
                    acc = ffma2(P[aa][0].y, C0[cc].y, acc);
                    acc = ffma2(P[aa][1].x, C1[cc].x, acc);
                    acc = ffma2(P[aa][1].y, C1[cc].y, acc);
                    s[aa * 4 + cc] = pairsum(acc);
                }
            }
            float v1 = fold8(s[0], s[1], s[2], s[3], s[4], s[5], s[6], s[7], lane);
            float v2 = fold8(s[8], s[9], s[10], s[11], s[12], s[13], s[14], s[15], lane);
            if (writer) {
                float icn = icn_s[j0 + c];
                cost_s[(i0 + a)     * NP1 + (j0 + c)] = 1.0f - v1 * ipn1 * icn;
                cost_s[(i0 + 2 + a) * NP1 + (j0 + c)] = 1.0f - v2 * ipn2 * icn;
            }
        }
    }
    __syncthreads();

    // ---- D: JV Hungarian (warp 0; validated formulation) ----
    if (w == 0) {
        const unsigned ENC_INF = fenc(INFX);
        float u = 0.0f, v = 0.0f;
        int p = -1;

        for (int i = 0; i < NB; i++) {
            if (lane == NB) p = i;        // virtual start column holds new row
            float minv = INFX;
            int   way  = 0;
            bool  used = false;
            bool  row_used = false;
            int   j0  = NB;
            int   pj0 = i;

            while (true) {
                used     = used     || (lane == j0);
                row_used = row_used || (lane == pj0);
                float u_i0 = __shfl_sync(FULL, u, pj0);
                float crow = (lane < NB) ? cost_s[pj0 * NP1 + lane] : 0.0f;
                bool  act  = (lane < NB) && !used;
                if (act) {
                    float cv = crow - u_i0 - v;       // reduced cost
                    if (cv < minv) { minv = cv; way = j0; }
                }
                unsigned key  = act ? fenc(minv) : ENC_INF;
                unsigned kmin = __reduce_min_sync(FULL, key);
                int j1 = __ffs(__ballot_sync(FULL, key == kmin)) - 1;
                float delta = fdec(kmin);
                if (used)     v    -= delta;
                if (row_used) u    += delta;
                if (act)      minv -= delta;
                j0  = j1;
                pj0 = __shfl_sync(FULL, p, j0);
                if (pj0 < 0) break;      // reached a free column
            }
            while (j0 != NB) {           // augment back to virtual column
                int jp = __shfl_sync(FULL, way, j0);
                int pv = __shfl_sync(FULL, p, jp);
                if (lane == j0) p = pv;
                j0 = jp;
            }
        }
        if (lane < NB) col_s[p] = lane;  // col index of row p[j] is j
    }
    __syncthreads();

    // ---- E: gather out rows from smem-resident slots ----
    {
        #pragma unroll
        for (int k = 0; k < 4; k++) {
            int rr = w + 6 * k;          // 6 warps x 4 rows = 24
            int src = col_s[rr];
            const float4* s4 = (const float4*)(slots_s + src * ND);
            float4*       o4 = (float4*)(ob + rr * ND);
            o4[lane]      = s4[lane];
            o4[lane + 32] = s4[lane + 32];
        }
    }
}

extern "C" void kernel_launch(void* const* d_in, const int* in_sizes, int n_in,
                              void* d_out, int out_size) {
    const float* slots = (const float*)d_in[0];
    const float* prev  = (const float*)d_in[1];
    float* out = (float*)d_out;
    int B = in_sizes[0] / (NB * ND);
    hungk<<<B, 192>>>(slots, prev, out);
}

// round 6
// speedup vs baseline: 1.3596x; 1.3596x over previous
#include <cuda_runtime.h>
#include <cstdint>

#define NB    24
#define NP1   25
#define NCOST (NB * NP1)      // 600 floats per batch
#define ND    256
#define INFX  1e9f
#define FULL  0xffffffffu
#define MAXB  2048

// cost scratch: [B][24][25] fp32 (~4.9 MB), static device array (no allocs)
__device__ float g_cost[(size_t)MAXB * NCOST];

// packed fp32x2 FMA (sm_100+); doubles are 64-bit carriers for f32 pairs
__device__ __forceinline__ double ffma2(double a, double b, double c) {
    double r;
    asm("fma.rn.f32x2 %0, %1, %2, %3;" : "=d"(r) : "d"(a), "d"(b), "d"(c));
    return r;
}
__device__ __forceinline__ float pairsum(double a) {
    return __int_as_float(__double2loint(a)) + __int_as_float(__double2hiint(a));
}
// order-preserving float<->uint for unsigned min-reduction
__device__ __forceinline__ unsigned fenc(float x) {
    unsigned b = __float_as_uint(x);
    return b ^ (((unsigned)((int)b >> 31)) | 0x80000000u);
}
__device__ __forceinline__ float fdec(unsigned k) {
    unsigned m = ((unsigned)((int)(~k) >> 31)) | 0x80000000u;
    return __uint_as_float(k ^ m);
}

// 8-stream folded warp reduction: lane L ends holding the full sum of stream
// m(L) = bit4(L) | bit3(L)<<1 | bit2(L)<<2. 15 shfls, 8-wide ILP at the top.
__device__ __forceinline__ float fold8(
    float q0, float q1, float q2, float q3,
    float q4, float q5, float q6, float q7, int lane)
{
    q0 += __shfl_xor_sync(FULL, q0, 16);
    q1 += __shfl_xor_sync(FULL, q1, 16);
    q2 += __shfl_xor_sync(FULL, q2, 16);
    q3 += __shfl_xor_sync(FULL, q3, 16);
    q4 += __shfl_xor_sync(FULL, q4, 16);
    q5 += __shfl_xor_sync(FULL, q5, 16);
    q6 += __shfl_xor_sync(FULL, q6, 16);
    q7 += __shfl_xor_sync(FULL, q7, 16);
    float t0 = (lane & 16) ? q1 : q0;
    float t1 = (lane & 16) ? q3 : q2;
    float t2 = (lane & 16) ? q5 : q4;
    float t3 = (lane & 16) ? q7 : q6;
    t0 += __shfl_xor_sync(FULL, t0, 8);
    t1 += __shfl_xor_sync(FULL, t1, 8);
    t2 += __shfl_xor_sync(FULL, t2, 8);
    t3 += __shfl_xor_sync(FULL, t3, 8);
    float u0 = (lane & 8) ? t1 : t0;
    float u1 = (lane & 8) ? t3 : t2;
    u0 += __shfl_xor_sync(FULL, u0, 4);
    u1 += __shfl_xor_sync(FULL, u1, 4);
    float v = (lane & 4) ? u1 : u0;
    v += __shfl_xor_sync(FULL, v, 2);
    v += __shfl_xor_sync(FULL, v, 1);
    return v;
}

// ============================================================================
// Kernel 1 (cost): CTA = one batch, 192 threads (6 warps).
// Warp w owns i-block w: 4 prev rows LOADED ONCE into registers.
// Cur rows are read from global through L1 (6x CTA-local reuse hits L1; no
// smem staging, no extra barrier). Norms hoisted: one fold8 per warp computes
// 4 prev + 4 cur inverse norms -> smem. Then 6 j-blocks of 4: 16 dots via
// ffma2 in two 8-stream halves (register pressure), fold8 each, writers emit
// cost entries straight to g_cost.
// ============================================================================
__global__ __launch_bounds__(192) void costk(
    const float* __restrict__ slots,
    const float* __restrict__ prev,
    int B)
{
    __shared__ float ipn_s[NB];
    __shared__ float icn_s[NB];

    const int tid  = threadIdx.x;
    const int lane = tid & 31;
    const int w    = tid >> 5;           // 0..5
    const int b    = blockIdx.x;

    const float* sb = slots + (size_t)b * NB * ND;
    const float* pb = prev  + (size_t)b * NB * ND;

    // ---- prev i-block into registers + all inverse norms (one fold8) ----
    const int i0 = w * 4;
    double2 P[4][2];
    {
        float np[4], nc[4];
        #pragma unroll
        for (int r = 0; r < 4; r++) {
            const double2* pr = (const double2*)(pb + (i0 + r) * ND);
            P[r][0] = pr[lane];
            P[r][1] = pr[lane + 32];
            double an = 0.0;
            an = ffma2(P[r][0].x, P[r][0].x, an);
            an = ffma2(P[r][0].y, P[r][0].y, an);
            an = ffma2(P[r][1].x, P[r][1].x, an);
            an = ffma2(P[r][1].y, P[r][1].y, an);
            np[r] = pairsum(an);
            const double2* cr = (const double2*)(sb + (i0 + r) * ND);
            double2 c0 = cr[lane], c1 = cr[lane + 32];
            double cn = 0.0;
            cn = ffma2(c0.x, c0.x, cn);
            cn = ffma2(c0.y, c0.y, cn);
            cn = ffma2(c1.x, c1.x, cn);
            cn = ffma2(c1.y, c1.y, cn);
            nc[r] = pairsum(cn);
        }
        float v3 = fold8(np[0], np[1], np[2], np[3],
                         nc[0], nc[1], nc[2], nc[3], lane);
        float inv = 1.0f / fmaxf(sqrtf(v3), 1e-12f);
        if ((lane & 3) == 0) {
            int m = ((lane >> 4) & 1) | (((lane >> 3) & 1) << 1) | (((lane >> 2) & 1) << 2);
            if (m < 4) ipn_s[i0 + m]       = inv;
            else       icn_s[i0 + (m - 4)] = inv;
        }
    }
    __syncthreads();

    // ---- 6 j-blocks of 4 cur rows (global/L1), two 8-dot halves each ----
    {
        const int m = ((lane >> 4) & 1) | (((lane >> 3) & 1) << 1) | (((lane >> 2) & 1) << 2);
        const int a = m >> 2;       // 0..1
        const int c = m & 3;        // 0..3
        const bool writer = ((lane & 3) == 0);
        float ipn1 = 0.f, ipn2 = 0.f;
        if (writer) {
            ipn1 = ipn_s[i0 + a];
            ipn2 = ipn_s[i0 + 2 + a];
        }
        float* gc = g_cost + (size_t)b * NCOST;

        #pragma unroll
        for (int t = 0; t < 6; t++) {
            const int j0 = t * 4;
            double2 C0[4], C1[4];
            #pragma unroll
            for (int r = 0; r < 4; r++) {
                const double2* cr = (const double2*)(sb + (j0 + r) * ND);
                C0[r] = cr[lane];
                C1[r] = cr[lane + 32];
            }
            // half 1: rows a=0,1
            {
                float s[8];
                #pragma unroll
                for (int aa = 0; aa < 2; aa++) {
                    #pragma unroll
                    for (int cc = 0; cc < 4; cc++) {
                        double acc = 0.0;
                        acc = ffma2(P[aa][0].x, C0[cc].x, acc);
                        acc = ffma2(P[aa][0].y, C0[cc].y, acc);
                        acc = ffma2(P[aa][1].x, C1[cc].x, acc);
                        acc = ffma2(P[aa][1].y, C1[cc].y, acc);
                        s[aa * 4 + cc] = pairsum(acc);
                    }
                }
                float v1 = fold8(s[0], s[1], s[2], s[3], s[4], s[5], s[6], s[7], lane);
                if (writer)
                    gc[(i0 + a) * NP1 + (j0 + c)] = 1.0f - v1 * ipn1 * icn_s[j0 + c];
            }
            // half 2: rows a=2,3
            {
                float s[8];
                #pragma unroll
                for (int aa = 0; aa < 2; aa++) {
                    #pragma unroll
                    for (int cc = 0; cc < 4; cc++) {
                        double acc = 0.0;
                        acc = ffma2(P[2 + aa][0].x, C0[cc].x, acc);
                        acc = ffma2(P[2 + aa][0].y, C0[cc].y, acc);
                        acc = ffma2(P[2 + aa][1].x, C1[cc].x, acc);
                        acc = ffma2(P[2 + aa][1].y, C1[cc].y, acc);
                        s[aa * 4 + cc] = pairsum(acc);
                    }
                }
                float v2 = fold8(s[0], s[1], s[2], s[3], s[4], s[5], s[6], s[7], lane);
                if (writer)
                    gc[(i0 + 2 + a) * NP1 + (j0 + c)] = 1.0f - v2 * ipn2 * icn_s[j0 + c];
            }
        }
    }
}

// ============================================================================
// Kernel 2: JV Hungarian + gather (unchanged, validated). One warp per batch,
// 4 warps/CTA, no __syncthreads.
// ============================================================================
__global__ __launch_bounds__(128) void jvk(
    const float* __restrict__ slots,
    float* __restrict__ out,
    int B)
{
    __shared__ float cost_s[4][NCOST];
    __shared__ int   col_s[4][NB];

    const int lane = threadIdx.x & 31;
    const int w    = threadIdx.x >> 5;
    const int b    = blockIdx.x * 4 + w;
    if (b >= B) return;

    // ---- stage this batch's cost matrix into smem (600 floats) ----
    {
        const float4* gc4 = (const float4*)(g_cost + (size_t)b * NCOST);
        float4* cs4 = (float4*)cost_s[w];
        #pragma unroll
        for (int t = lane; t < NCOST / 4; t += 32)
            cs4[t] = gc4[t];
    }
    __syncwarp();

    // ---- JV Hungarian: lane j owns column j; u,v in lane registers ----
    {
        const float* cw = cost_s[w];
        const unsigned ENC_INF = fenc(INFX);
        float u = 0.0f, v = 0.0f;
        int p = -1;

        for (int i = 0; i < NB; i++) {
            if (lane == NB) p = i;        // virtual start column holds new row
            float minv = INFX;
            int   way  = 0;
            bool  used = false;
            bool  row_used = false;
            int   j0  = NB;
            int   pj0 = i;

            while (true) {
                used     = used     || (lane == j0);
                row_used = row_used || (lane == pj0);
                float u_i0 = __shfl_sync(FULL, u, pj0);
                float crow = (lane < NB) ? cw[pj0 * NP1 + lane] : 0.0f;
                bool  act  = (lane < NB) && !used;
                if (act) {
                    float cv = crow - u_i0 - v;       // reduced cost
                    if (cv < minv) { minv = cv; way = j0; }
                }
                unsigned key  = act ? fenc(minv) : ENC_INF;
                unsigned kmin = __reduce_min_sync(FULL, key);
                int j1 = __ffs(__ballot_sync(FULL, key == kmin)) - 1;
                float delta = fdec(kmin);
                if (used)     v    -= delta;
                if (row_used) u    += delta;
                if (act)      minv -= delta;
                j0  = j1;
                pj0 = __shfl_sync(FULL, p, j0);
                if (pj0 < 0) break;      // reached a free column
            }
            // augment along parent pointers back to virtual column
            while (j0 != NB) {
                int jp = __shfl_sync(FULL, way, j0);
                int pv = __shfl_sync(FULL, p, jp);
                if (lane == j0) p = pv;
                j0 = jp;
            }
        }
        if (lane < NB) col_s[w][p] = lane;   // col index of row p[j] is j
    }
    __syncwarp();

    // ---- gather: out[row][:] = slots[col[row]][:] ----
    const float* sb = slots + (size_t)b * NB * ND;
    float*       ob = out   + (size_t)b * NB * ND;
    for (int rr = 0; rr < NB; rr++) {
        int src = col_s[w][rr];
        const float4* s4 = (const float4*)(sb + src * ND);
        float4*       o4 = (float4*)(ob + rr * ND);
        o4[lane]      = s4[lane];
        o4[lane + 32] = s4[lane + 32];
    }
}

extern "C" void kernel_launch(void* const* d_in, const int* in_sizes, int n_in,
                              void* d_out, int out_size) {
    const float* slots = (const float*)d_in[0];
    const float* prev  = (const float*)d_in[1];
    float* out = (float*)d_out;
    int B = in_sizes[0] / (NB * ND);
    if (B > MAXB) B = MAXB;

    costk<<<B, 192>>>(slots, prev, B);

    int grid2 = (B + 3) / 4;
    jvk<<<grid2, 128>>>(slots, out, B);
}